// round 6
// baseline (speedup 1.0000x reference)
#include <cuda_runtime.h>
#include <math.h>

// ---------------- scratch (device globals; no allocation allowed) ----------
#define MAXN 100352
#define MAXE 1700000

__device__ int   g_is64;
__device__ int   g_src[MAXE];
__device__ int   g_dst[MAXE];
__device__ int   g_count[MAXN];
__device__ int   g_fill[MAXN];
__device__ int   g_rowptr[MAXN + 1];
__device__ float g_dinv[MAXN];
__device__ int   g_csr[MAXE];
__device__ float g_bufA[(size_t)MAXN * 128];   // hs1 = (x@W1)*dinv  (pre-agg, scaled)
__device__ float g_bufB[(size_t)MAXN * 128];   // h1r = relu(agg1*dinv + b1)
__device__ float g_bufC[(size_t)MAXN * 16];    // hs2 = (h1r@W2)*dinv, padded to 16 cols

__device__ __forceinline__ float4 f4add(float4 a, float4 b) {
    return make_float4(a.x + b.x, a.y + b.y, a.z + b.z, a.w + b.w);
}

// ---------------- index dtype detection + conversion -----------------------
// If the edge_index buffer is int32 (JAX default, x64 disabled), interpreting
// it as int64 yields values lo + hi*2^32 that fall outside [0, N) with
// probability ~1 - 1e-5 per sample. 4096 samples -> certain detection.
__global__ void k_detect(const void* __restrict__ ei, int E, int N) {
    __shared__ int ok;
    if (threadIdx.x == 0) ok = 1;
    __syncthreads();
    const long long* p = (const long long*)ei;
    int step = E / 4096;
    if (step < 1) step = 1;
    for (int i = threadIdx.x; i < 4096; i += blockDim.x) {
        long long idx = (long long)i * step;
        if (idx < E) {
            long long v = p[idx];     // within first half (src row) if int64;
                                      // within buffer bounds either way
            if (v < 0 || v >= N) ok = 0;
        }
    }
    __syncthreads();
    if (threadIdx.x == 0) g_is64 = ok;
}

__global__ void k_convert(const void* __restrict__ ei, int E) {
    int e = blockIdx.x * blockDim.x + threadIdx.x;
    if (e >= E) return;
    if (g_is64) {
        const long long* p = (const long long*)ei;
        g_src[e] = (int)p[e];
        g_dst[e] = (int)p[e + E];
    } else {
        const int* p = (const int*)ei;
        g_src[e] = p[e];
        g_dst[e] = p[e + E];
    }
}

// ---------------- CSR build ------------------------------------------------
__global__ void k_zero(int n) {
    int i = blockIdx.x * blockDim.x + threadIdx.x;
    if (i < n) { g_count[i] = 0; g_fill[i] = 0; }
}

__global__ void k_count(int E) {
    int e = blockIdx.x * blockDim.x + threadIdx.x;
    if (e < E) atomicAdd(&g_count[g_dst[e]], 1);
}

// single-block exclusive scan of g_count -> g_rowptr; also dinv = rsqrt(deg+1)
__global__ void k_scan(int n) {
    __shared__ int wsum[32];
    __shared__ int run;
    int tid = threadIdx.x, lane = tid & 31, w = tid >> 5;
    if (tid == 0) run = 0;
    __syncthreads();
    for (int base = 0; base < n; base += 1024) {
        int i = base + tid;
        int v = (i < n) ? g_count[i] : 0;
        int x = v;
        #pragma unroll
        for (int off = 1; off < 32; off <<= 1) {
            int y = __shfl_up_sync(0xffffffffu, x, off);
            if (lane >= off) x += y;
        }
        if (lane == 31) wsum[w] = x;
        __syncthreads();
        if (w == 0) {
            int s = wsum[lane];
            #pragma unroll
            for (int off = 1; off < 32; off <<= 1) {
                int y = __shfl_up_sync(0xffffffffu, s, off);
                if (lane >= off) s += y;
            }
            wsum[lane] = s;
        }
        __syncthreads();
        int incl = x + (w > 0 ? wsum[w - 1] : 0) + run;
        if (i < n) {
            g_rowptr[i] = incl - v;                       // exclusive
            g_dinv[i]   = rsqrtf((float)v + 1.0f);        // self-loop degree
        }
        __syncthreads();
        if (tid == 1023) run = incl;
        __syncthreads();
    }
    if (threadIdx.x == 0) g_rowptr[n] = run;
}

__global__ void k_scatter(int E) {
    int e = blockIdx.x * blockDim.x + threadIdx.x;
    if (e < E) {
        int d = g_dst[e];
        int pos = g_rowptr[d] + atomicAdd(&g_fill[d], 1);
        g_csr[pos] = g_src[e];
    }
}

// ---------------- GEMM1: hs1 = (x @ W1) * dinv[row] ------------------------
// block: 128 rows x 128 cols, 256 threads, 8x8 microtile, full K=128 in smem
__global__ void k_gemm1(const float* __restrict__ x,
                        const float* __restrict__ W, int n) {
    extern __shared__ float sm[];
    float* ws = sm;           // [k][c] 128x128
    float* xs = sm + 16384;   // [k][r] 128x128 (transposed x tile)
    int tid = threadIdx.x;
    int row0 = blockIdx.x * 128;

    for (int i = tid; i < 4096; i += 256)
        ((float4*)ws)[i] = ((const float4*)W)[i];

    for (int i = tid; i < 4096; i += 256) {
        int k4 = i >> 7, r = i & 127;
        float4 v = make_float4(0.f, 0.f, 0.f, 0.f);
        int row = row0 + r;
        if (row < n) v = ((const float4*)x)[(size_t)row * 32 + k4];
        xs[(k4 * 4 + 0) * 128 + r] = v.x;
        xs[(k4 * 4 + 1) * 128 + r] = v.y;
        xs[(k4 * 4 + 2) * 128 + r] = v.z;
        xs[(k4 * 4 + 3) * 128 + r] = v.w;
    }
    __syncthreads();

    int tx = tid & 15, ty = tid >> 4;
    float acc[8][8];
    #pragma unroll
    for (int i = 0; i < 8; i++)
        #pragma unroll
        for (int j = 0; j < 8; j++) acc[i][j] = 0.f;

    #pragma unroll 4
    for (int k = 0; k < 128; k++) {
        float4 a0 = *(const float4*)&xs[k * 128 + ty * 8];
        float4 a1 = *(const float4*)&xs[k * 128 + ty * 8 + 4];
        float4 b0 = *(const float4*)&ws[k * 128 + tx * 8];
        float4 b1 = *(const float4*)&ws[k * 128 + tx * 8 + 4];
        float a[8] = {a0.x, a0.y, a0.z, a0.w, a1.x, a1.y, a1.z, a1.w};
        float b[8] = {b0.x, b0.y, b0.z, b0.w, b1.x, b1.y, b1.z, b1.w};
        #pragma unroll
        for (int i = 0; i < 8; i++)
            #pragma unroll
            for (int j = 0; j < 8; j++)
                acc[i][j] = fmaf(a[i], b[j], acc[i][j]);
    }

    #pragma unroll
    for (int i = 0; i < 8; i++) {
        int row = row0 + ty * 8 + i;
        if (row < n) {
            float di = g_dinv[row];
            float4 o0 = make_float4(acc[i][0] * di, acc[i][1] * di,
                                    acc[i][2] * di, acc[i][3] * di);
            float4 o1 = make_float4(acc[i][4] * di, acc[i][5] * di,
                                    acc[i][6] * di, acc[i][7] * di);
            ((float4*)g_bufA)[(size_t)row * 32 + tx * 2]     = o0;
            ((float4*)g_bufA)[(size_t)row * 32 + tx * 2 + 1] = o1;
        }
    }
}

// ---------------- Agg1: h1r = relu(dinv[d]*(hs1[d] + sum_in hs1[s]) + b1) --
__global__ void k_agg1(const float* __restrict__ b1, int n) {
    int w = (blockIdx.x * blockDim.x + threadIdx.x) >> 5;
    int lane = threadIdx.x & 31;
    if (w >= n) return;
    int d = w;
    const float4* A = (const float4*)g_bufA;
    float4 acc0 = A[(size_t)d * 32 + lane];    // self loop
    float4 acc1 = make_float4(0, 0, 0, 0);
    float4 acc2 = make_float4(0, 0, 0, 0);
    float4 acc3 = make_float4(0, 0, 0, 0);
    int beg = g_rowptr[d], end = g_rowptr[d + 1];
    int e = beg;
    for (; e + 4 <= end; e += 4) {
        int s0 = g_csr[e], s1 = g_csr[e + 1], s2 = g_csr[e + 2], s3 = g_csr[e + 3];
        acc0 = f4add(acc0, A[(size_t)s0 * 32 + lane]);
        acc1 = f4add(acc1, A[(size_t)s1 * 32 + lane]);
        acc2 = f4add(acc2, A[(size_t)s2 * 32 + lane]);
        acc3 = f4add(acc3, A[(size_t)s3 * 32 + lane]);
    }
    for (; e < end; e++)
        acc0 = f4add(acc0, A[(size_t)g_csr[e] * 32 + lane]);
    float4 acc = f4add(f4add(acc0, acc1), f4add(acc2, acc3));
    float di = g_dinv[d];
    float4 bb = ((const float4*)b1)[lane];
    float4 r;
    r.x = fmaxf(fmaf(acc.x, di, bb.x), 0.f);
    r.y = fmaxf(fmaf(acc.y, di, bb.y), 0.f);
    r.z = fmaxf(fmaf(acc.z, di, bb.z), 0.f);
    r.w = fmaxf(fmaf(acc.w, di, bb.w), 0.f);
    ((float4*)g_bufB)[(size_t)d * 32 + lane] = r;
}

// ---------------- GEMM2: hs2 = (h1r @ W2) * dinv, warp per row -------------
__global__ void k_gemm2(const float* __restrict__ W2, int n) {
    __shared__ float w2t[10 * 128];   // [c][k]
    int tid = threadIdx.x;
    for (int i = tid; i < 1280; i += 256) {
        int k = i / 10, c = i % 10;   // W2 row-major [k][c]
        w2t[c * 128 + k] = W2[i];
    }
    __syncthreads();
    int w = (blockIdx.x * blockDim.x + tid) >> 5;
    int lane = tid & 31;
    if (w >= n) return;
    int r = w;
    float4 h = ((const float4*)g_bufB)[(size_t)r * 32 + lane];
    float p[10];
    #pragma unroll
    for (int c = 0; c < 10; c++) {
        float s = h.x * w2t[c * 128 + lane * 4]
                + h.y * w2t[c * 128 + lane * 4 + 1]
                + h.z * w2t[c * 128 + lane * 4 + 2]
                + h.w * w2t[c * 128 + lane * 4 + 3];
        #pragma unroll
        for (int off = 16; off; off >>= 1)
            s += __shfl_xor_sync(0xffffffffu, s, off);
        p[c] = s;
    }
    float di = g_dinv[r];
    float val = 0.f;
    #pragma unroll
    for (int c = 0; c < 10; c++)
        if (lane == c) val = p[c];
    if (lane < 16)
        g_bufC[(size_t)r * 16 + lane] = (lane < 10) ? val * di : 0.f;
}

// ---------------- Agg2 + bias + softmax, half-warp per node ----------------
__global__ void k_agg2(const float* __restrict__ b2, float* __restrict__ out, int n) {
    int tid = threadIdx.x;
    int hw = (blockIdx.x * blockDim.x + tid) >> 4;
    int c = tid & 15;
    if (hw >= n) return;
    int d = hw;
    const float* C = g_bufC;
    float acc0 = C[(size_t)d * 16 + c];   // self loop
    float acc1 = 0.f, acc2 = 0.f, acc3 = 0.f;
    int beg = g_rowptr[d], end = g_rowptr[d + 1];
    int e = beg;
    for (; e + 4 <= end; e += 4) {
        int s0 = g_csr[e], s1 = g_csr[e + 1], s2 = g_csr[e + 2], s3 = g_csr[e + 3];
        acc0 += C[(size_t)s0 * 16 + c];
        acc1 += C[(size_t)s1 * 16 + c];
        acc2 += C[(size_t)s2 * 16 + c];
        acc3 += C[(size_t)s3 * 16 + c];
    }
    for (; e < end; e++)
        acc0 += C[(size_t)g_csr[e] * 16 + c];
    float acc = (acc0 + acc1) + (acc2 + acc3);
    float bc = (c < 10) ? b2[c] : 0.f;
    float logit = (c < 10) ? fmaf(acc, g_dinv[d], bc) : -1e30f;
    float m = logit;
    #pragma unroll
    for (int off = 8; off; off >>= 1)
        m = fmaxf(m, __shfl_xor_sync(0xffffffffu, m, off));
    float ex = (c < 10) ? __expf(logit - m) : 0.f;
    float ssum = ex;
    #pragma unroll
    for (int off = 8; off; off >>= 1)
        ssum += __shfl_xor_sync(0xffffffffu, ssum, off);
    if (c < 10) out[(size_t)d * 10 + c] = ex / ssum;
}

// ---------------- launch ---------------------------------------------------
extern "C" void kernel_launch(void* const* d_in, const int* in_sizes, int n_in,
                              void* d_out, int out_size) {
    const float* x  = (const float*)d_in[0];
    const void*  ei = d_in[1];
    const float* W1 = (const float*)d_in[2];
    const float* b1 = (const float*)d_in[3];
    const float* W2 = (const float*)d_in[4];
    const float* b2 = (const float*)d_in[5];
    int N = in_sizes[0] / 128;
    int E = in_sizes[1] / 2;

    cudaFuncSetAttribute(k_gemm1, cudaFuncAttributeMaxDynamicSharedMemorySize, 131072);

    k_detect <<<1, 256>>>(ei, E, N);
    k_convert<<<(E + 255) / 256, 256>>>(ei, E);
    k_zero   <<<(N + 255) / 256, 256>>>(N);
    k_count  <<<(E + 255) / 256, 256>>>(E);
    k_scan   <<<1, 1024>>>(N);
    k_scatter<<<(E + 255) / 256, 256>>>(E);
    k_gemm1  <<<(N + 127) / 128, 256, 131072>>>(x, W1, N);
    k_agg1   <<<(N + 7) / 8, 256>>>(b1, N);
    k_gemm2  <<<(N + 7) / 8, 256>>>(W2, N);
    k_agg2   <<<(N + 15) / 16, 256>>>(b2, (float*)d_out, N);
}

// round 10
// speedup vs baseline: 1.0596x; 1.0596x over previous
#include <cuda_runtime.h>
#include <cuda_bf16.h>
#include <math.h>

// ---------------- scratch (device globals; no allocation allowed) ----------
#define MAXN 100352
#define MAXE 1700000

__device__ int   g_is64;
__device__ int   g_count[MAXN];
__device__ int   g_fill[MAXN];
__device__ int   g_rowptr[MAXN + 1];
__device__ float g_dinv[MAXN];
__device__ int   g_csr[MAXE];
__device__ __nv_bfloat16 g_bufA[(size_t)MAXN * 128]; // hs1 = (x@W1)*dinv (bf16)
__device__ float g_bufB[(size_t)MAXN * 128];         // h1r = relu(agg1*dinv + b1)
__device__ float g_bufC[(size_t)MAXN * 16];          // hs2 = (h1r@W2)*dinv, padded

// ---------------- index dtype detection ------------------------------------
// JAX may hand us int32 (x64 disabled) even though the reference says int64.
// Interpreted as int64, int32 data gives values lo + hi*2^32 outside [0,N)
// with prob ~1-1e-5 per sample; 4096 samples -> certain detection.
__global__ void k_detect(const void* __restrict__ ei, int E, int N) {
    __shared__ int ok;
    if (threadIdx.x == 0) ok = 1;
    __syncthreads();
    const long long* p = (const long long*)ei;
    int step = E / 4096;
    if (step < 1) step = 1;
    for (int i = threadIdx.x; i < 4096; i += blockDim.x) {
        long long idx = (long long)i * step;
        if (idx < E) {
            long long v = p[idx];
            if (v < 0 || v >= N) ok = 0;
        }
    }
    __syncthreads();
    if (threadIdx.x == 0) g_is64 = ok;
}

__device__ __forceinline__ int load_idx(const void* ei, long long pos) {
    if (g_is64) return (int)((const long long*)ei)[pos];
    return ((const int*)ei)[pos];
}

// ---------------- CSR build ------------------------------------------------
__global__ void k_zero(int n) {
    int i = blockIdx.x * blockDim.x + threadIdx.x;
    if (i < n) { g_count[i] = 0; g_fill[i] = 0; }
}

__global__ void k_count(const void* __restrict__ ei, int E) {
    int e = blockIdx.x * blockDim.x + threadIdx.x;
    if (e < E) atomicAdd(&g_count[load_idx(ei, (long long)e + E)], 1);
}

// single-block exclusive scan of g_count -> g_rowptr; also dinv = rsqrt(deg+1)
__global__ void k_scan(int n) {
    __shared__ int wsum[32];
    __shared__ int run;
    int tid = threadIdx.x, lane = tid & 31, w = tid >> 5;
    if (tid == 0) run = 0;
    __syncthreads();
    for (int base = 0; base < n; base += 1024) {
        int i = base + tid;
        int v = (i < n) ? g_count[i] : 0;
        int x = v;
        #pragma unroll
        for (int off = 1; off < 32; off <<= 1) {
            int y = __shfl_up_sync(0xffffffffu, x, off);
            if (lane >= off) x += y;
        }
        if (lane == 31) wsum[w] = x;
        __syncthreads();
        if (w == 0) {
            int s = wsum[lane];
            #pragma unroll
            for (int off = 1; off < 32; off <<= 1) {
                int y = __shfl_up_sync(0xffffffffu, s, off);
                if (lane >= off) s += y;
            }
            wsum[lane] = s;
        }
        __syncthreads();
        int incl = x + (w > 0 ? wsum[w - 1] : 0) + run;
        if (i < n) {
            g_rowptr[i] = incl - v;                       // exclusive
            g_dinv[i]   = rsqrtf((float)v + 1.0f);        // self-loop degree
        }
        __syncthreads();
        if (tid == 1023) run = incl;
        __syncthreads();
    }
    if (threadIdx.x == 0) g_rowptr[n] = run;
}

__global__ void k_scatter(const void* __restrict__ ei, int E) {
    int e = blockIdx.x * blockDim.x + threadIdx.x;
    if (e < E) {
        int d = load_idx(ei, (long long)e + E);
        int s = load_idx(ei, e);
        int pos = g_rowptr[d] + atomicAdd(&g_fill[d], 1);
        g_csr[pos] = s;
    }
}

// ---------------- GEMM1: hs1 = bf16((x @ W1) * dinv[row]) ------------------
// block: 128 rows x 128 cols, 256 threads, 8x8 microtile, full K=128 in smem
__global__ void k_gemm1(const float* __restrict__ x,
                        const float* __restrict__ W, int n) {
    extern __shared__ float sm[];
    float* ws = sm;           // [k][c] 128x128
    float* xs = sm + 16384;   // [k][r] 128x128 (transposed x tile)
    int tid = threadIdx.x;
    int row0 = blockIdx.x * 128;

    for (int i = tid; i < 4096; i += 256)
        ((float4*)ws)[i] = ((const float4*)W)[i];

    for (int i = tid; i < 4096; i += 256) {
        int k4 = i >> 7, r = i & 127;
        float4 v = make_float4(0.f, 0.f, 0.f, 0.f);
        int row = row0 + r;
        if (row < n) v = ((const float4*)x)[(size_t)row * 32 + k4];
        xs[(k4 * 4 + 0) * 128 + r] = v.x;
        xs[(k4 * 4 + 1) * 128 + r] = v.y;
        xs[(k4 * 4 + 2) * 128 + r] = v.z;
        xs[(k4 * 4 + 3) * 128 + r] = v.w;
    }
    __syncthreads();

    int tx = tid & 15, ty = tid >> 4;
    float acc[8][8];
    #pragma unroll
    for (int i = 0; i < 8; i++)
        #pragma unroll
        for (int j = 0; j < 8; j++) acc[i][j] = 0.f;

    #pragma unroll 4
    for (int k = 0; k < 128; k++) {
        float4 a0 = *(const float4*)&xs[k * 128 + ty * 8];
        float4 a1 = *(const float4*)&xs[k * 128 + ty * 8 + 4];
        float4 b0 = *(const float4*)&ws[k * 128 + tx * 8];
        float4 b1 = *(const float4*)&ws[k * 128 + tx * 8 + 4];
        float a[8] = {a0.x, a0.y, a0.z, a0.w, a1.x, a1.y, a1.z, a1.w};
        float b[8] = {b0.x, b0.y, b0.z, b0.w, b1.x, b1.y, b1.z, b1.w};
        #pragma unroll
        for (int i = 0; i < 8; i++)
            #pragma unroll
            for (int j = 0; j < 8; j++)
                acc[i][j] = fmaf(a[i], b[j], acc[i][j]);
    }

    #pragma unroll
    for (int i = 0; i < 8; i++) {
        int row = row0 + ty * 8 + i;
        if (row < n) {
            float di = g_dinv[row];
            // pack 8 scaled values to bf16 (4x __nv_bfloat162 -> uint4)
            __nv_bfloat162 p0 = __floats2bfloat162_rn(acc[i][0] * di, acc[i][1] * di);
            __nv_bfloat162 p1 = __floats2bfloat162_rn(acc[i][2] * di, acc[i][3] * di);
            __nv_bfloat162 p2 = __floats2bfloat162_rn(acc[i][4] * di, acc[i][5] * di);
            __nv_bfloat162 p3 = __floats2bfloat162_rn(acc[i][6] * di, acc[i][7] * di);
            uint4 pk;
            pk.x = *(unsigned int*)&p0;
            pk.y = *(unsigned int*)&p1;
            pk.z = *(unsigned int*)&p2;
            pk.w = *(unsigned int*)&p3;
            // row stride = 128 bf16 = 16 uint4; tx in [0,16)
            ((uint4*)g_bufA)[(size_t)row * 16 + tx] = pk;
        }
    }
}

// ---------------- Agg1: h1r = relu(dinv[d]*(hs1[d] + sum_in hs1[s]) + b1) --
// warp per node; lane covers 4 cols (8B bf16 = uint2 per row-slice)
__device__ __forceinline__ void bf4_acc(float* a, uint2 v) {
    __nv_bfloat162 lo = *(__nv_bfloat162*)&v.x;
    __nv_bfloat162 hi = *(__nv_bfloat162*)&v.y;
    float2 f0 = __bfloat1622float2(lo);
    float2 f1 = __bfloat1622float2(hi);
    a[0] += f0.x; a[1] += f0.y; a[2] += f1.x; a[3] += f1.y;
}

__global__ void k_agg1(const float* __restrict__ b1, int n) {
    int w = (blockIdx.x * blockDim.x + threadIdx.x) >> 5;
    int lane = threadIdx.x & 31;
    if (w >= n) return;
    int d = w;
    const uint2* A = (const uint2*)g_bufA;   // row stride = 32 uint2
    float a0[4] = {0, 0, 0, 0}, a1[4] = {0, 0, 0, 0};
    float a2[4] = {0, 0, 0, 0}, a3[4] = {0, 0, 0, 0};
    bf4_acc(a0, A[(size_t)d * 32 + lane]);   // self loop
    int beg = g_rowptr[d], end = g_rowptr[d + 1];
    int e = beg;
    for (; e + 4 <= end; e += 4) {
        int s0 = g_csr[e], s1 = g_csr[e + 1], s2 = g_csr[e + 2], s3 = g_csr[e + 3];
        uint2 v0 = A[(size_t)s0 * 32 + lane];
        uint2 v1 = A[(size_t)s1 * 32 + lane];
        uint2 v2 = A[(size_t)s2 * 32 + lane];
        uint2 v3 = A[(size_t)s3 * 32 + lane];
        bf4_acc(a0, v0); bf4_acc(a1, v1); bf4_acc(a2, v2); bf4_acc(a3, v3);
    }
    for (; e < end; e++)
        bf4_acc(a0, A[(size_t)g_csr[e] * 32 + lane]);
    float di = g_dinv[d];
    float4 bb = ((const float4*)b1)[lane];
    float4 r;
    r.x = fmaxf(fmaf((a0[0] + a1[0]) + (a2[0] + a3[0]), di, bb.x), 0.f);
    r.y = fmaxf(fmaf((a0[1] + a1[1]) + (a2[1] + a3[1]), di, bb.y), 0.f);
    r.z = fmaxf(fmaf((a0[2] + a1[2]) + (a2[2] + a3[2]), di, bb.z), 0.f);
    r.w = fmaxf(fmaf((a0[3] + a1[3]) + (a2[3] + a3[3]), di, bb.w), 0.f);
    ((float4*)g_bufB)[(size_t)d * 32 + lane] = r;
}

// ---------------- GEMM2: hs2 = (h1r @ W2) * dinv, warp per row -------------
__global__ void k_gemm2(const float* __restrict__ W2, int n) {
    __shared__ float w2t[10 * 128];   // [c][k]
    int tid = threadIdx.x;
    for (int i = tid; i < 1280; i += 256) {
        int k = i / 10, c = i % 10;   // W2 row-major [k][c]
        w2t[c * 128 + k] = W2[i];
    }
    __syncthreads();
    int w = (blockIdx.x * blockDim.x + tid) >> 5;
    int lane = tid & 31;
    if (w >= n) return;
    int r = w;
    float4 h = ((const float4*)g_bufB)[(size_t)r * 32 + lane];
    float p[10];
    #pragma unroll
    for (int c = 0; c < 10; c++) {
        float s = h.x * w2t[c * 128 + lane * 4]
                + h.y * w2t[c * 128 + lane * 4 + 1]
                + h.z * w2t[c * 128 + lane * 4 + 2]
                + h.w * w2t[c * 128 + lane * 4 + 3];
        #pragma unroll
        for (int off = 16; off; off >>= 1)
            s += __shfl_xor_sync(0xffffffffu, s, off);
        p[c] = s;
    }
    float di = g_dinv[r];
    float val = 0.f;
    #pragma unroll
    for (int c = 0; c < 10; c++)
        if (lane == c) val = p[c];
    if (lane < 16)
        g_bufC[(size_t)r * 16 + lane] = (lane < 10) ? val * di : 0.f;
}

// ---------------- Agg2 + bias + softmax, half-warp per node ----------------
__global__ void k_agg2(const float* __restrict__ b2, float* __restrict__ out, int n) {
    int tid = threadIdx.x;
    int hw = (blockIdx.x * blockDim.x + tid) >> 4;
    int c = tid & 15;
    if (hw >= n) return;
    int d = hw;
    const float* C = g_bufC;
    float acc0 = C[(size_t)d * 16 + c];   // self loop
    float acc1 = 0.f, acc2 = 0.f, acc3 = 0.f;
    int beg = g_rowptr[d], end = g_rowptr[d + 1];
    int e = beg;
    for (; e + 4 <= end; e += 4) {
        int s0 = g_csr[e], s1 = g_csr[e + 1], s2 = g_csr[e + 2], s3 = g_csr[e + 3];
        acc0 += C[(size_t)s0 * 16 + c];
        acc1 += C[(size_t)s1 * 16 + c];
        acc2 += C[(size_t)s2 * 16 + c];
        acc3 += C[(size_t)s3 * 16 + c];
    }
    for (; e < end; e++)
        acc0 += C[(size_t)g_csr[e] * 16 + c];
    float acc = (acc0 + acc1) + (acc2 + acc3);
    float bc = (c < 10) ? b2[c] : 0.f;
    float logit = (c < 10) ? fmaf(acc, g_dinv[d], bc) : -1e30f;
    float m = logit;
    #pragma unroll
    for (int off = 8; off; off >>= 1)
        m = fmaxf(m, __shfl_xor_sync(0xffffffffu, m, off));
    float ex = (c < 10) ? __expf(logit - m) : 0.f;
    float ssum = ex;
    #pragma unroll
    for (int off = 8; off; off >>= 1)
        ssum += __shfl_xor_sync(0xffffffffu, ssum, off);
    if (c < 10) out[(size_t)d * 10 + c] = ex / ssum;
}

// ---------------- launch ---------------------------------------------------
extern "C" void kernel_launch(void* const* d_in, const int* in_sizes, int n_in,
                              void* d_out, int out_size) {
    const float* x  = (const float*)d_in[0];
    const void*  ei = d_in[1];
    const float* W1 = (const float*)d_in[2];
    const float* b1 = (const float*)d_in[3];
    const float* W2 = (const float*)d_in[4];
    const float* b2 = (const float*)d_in[5];
    int N = in_sizes[0] / 128;
    int E = in_sizes[1] / 2;

    cudaFuncSetAttribute(k_gemm1, cudaFuncAttributeMaxDynamicSharedMemorySize, 131072);

    k_detect <<<1, 256>>>(ei, E, N);
    k_zero   <<<(N + 255) / 256, 256>>>(N);
    k_count  <<<(E + 255) / 256, 256>>>(ei, E);
    k_scan   <<<1, 1024>>>(N);
    k_scatter<<<(E + 255) / 256, 256>>>(ei, E);
    k_gemm1  <<<(N + 127) / 128, 256, 131072>>>(x, W1, N);
    k_agg1   <<<(N + 7) / 8, 256>>>(b1, N);
    k_gemm2  <<<(N + 7) / 8, 256>>>(W2, N);
    k_agg2   <<<(N + 15) / 16, 256>>>(b2, (float*)d_out, N);
}

// round 11
// speedup vs baseline: 1.2933x; 1.2206x over previous
#include <cuda_runtime.h>
#include <cuda_bf16.h>
#include <math.h>

// ---------------- scratch (device globals; no allocation allowed) ----------
#define MAXN 100352
#define MAXE 1700000
#define SCAN_B 1024                      // elements per scan block
#define MAXNB ((MAXN + SCAN_B - 1) / SCAN_B)

__device__ int   g_is64;
__device__ int   g_count[MAXN];
__device__ int   g_fill[MAXN];
__device__ int   g_rowptr[MAXN + 1];
__device__ int   g_bsum[MAXNB];
__device__ float g_dinv[MAXN];
__device__ int   g_csr[MAXE];
__device__ __nv_bfloat16 g_bufA[(size_t)MAXN * 128]; // hs1 = (x@W1)*dinv (bf16)
__device__ float g_bufB[(size_t)MAXN * 128];         // h1r = relu(agg1*dinv + b1)
__device__ float g_bufC[(size_t)MAXN * 16];          // hs2 = (h1r@W2)*dinv, padded

// ---------------- index dtype detection ------------------------------------
// JAX may hand us int32 (x64 disabled) even though the reference says int64.
// Interpreted as int64, int32 data gives values lo + hi*2^32 outside [0,N)
// with prob ~1-1e-5 per sample; 4096 samples -> certain detection.
__global__ void k_detect(const void* __restrict__ ei, int E, int N) {
    __shared__ int ok;
    if (threadIdx.x == 0) ok = 1;
    __syncthreads();
    const long long* p = (const long long*)ei;
    int step = E / 4096;
    if (step < 1) step = 1;
    for (int i = threadIdx.x; i < 4096; i += blockDim.x) {
        long long idx = (long long)i * step;
        if (idx < E) {
            long long v = p[idx];
            if (v < 0 || v >= N) ok = 0;
        }
    }
    __syncthreads();
    if (threadIdx.x == 0) g_is64 = ok;
}

__device__ __forceinline__ int load_idx(const void* ei, long long pos) {
    if (g_is64) return (int)((const long long*)ei)[pos];
    return ((const int*)ei)[pos];
}

// ---------------- CSR build ------------------------------------------------
__global__ void k_zero(int n) {
    int i = blockIdx.x * blockDim.x + threadIdx.x;
    if (i < n) { g_count[i] = 0; g_fill[i] = 0; }
}

__global__ void k_count(const void* __restrict__ ei, int E) {
    int e = blockIdx.x * blockDim.x + threadIdx.x;
    if (e < E) atomicAdd(&g_count[load_idx(ei, (long long)e + E)], 1);
}

// Phase A: per-block exclusive scan + block totals; also dinv = rsqrt(deg+1)
__global__ void k_scanA(int n) {
    __shared__ int wsum[32];
    int tid = threadIdx.x, lane = tid & 31, w = tid >> 5;
    int i = blockIdx.x * SCAN_B + tid;
    int v = (i < n) ? g_count[i] : 0;
    int x = v;
    #pragma unroll
    for (int off = 1; off < 32; off <<= 1) {
        int y = __shfl_up_sync(0xffffffffu, x, off);
        if (lane >= off) x += y;
    }
    if (lane == 31) wsum[w] = x;
    __syncthreads();
    if (w == 0) {
        int s = wsum[lane];
        #pragma unroll
        for (int off = 1; off < 32; off <<= 1) {
            int y = __shfl_up_sync(0xffffffffu, s, off);
            if (lane >= off) s += y;
        }
        wsum[lane] = s;
    }
    __syncthreads();
    int incl = x + (w > 0 ? wsum[w - 1] : 0);
    if (i < n) {
        g_rowptr[i] = incl - v;                  // block-local exclusive
        g_dinv[i]   = rsqrtf((float)v + 1.0f);   // self-loop degree
    }
    if (tid == SCAN_B - 1) g_bsum[blockIdx.x] = incl;
}

// Phase B: one warp scans the block totals (nb <= 128), writes rowptr[n]
__global__ void k_scanB(int nb, int n) {
    int lane = threadIdx.x;
    int run = 0;
    for (int base = 0; base < nb; base += 32) {
        int i = base + lane;
        int v = (i < nb) ? g_bsum[i] : 0;
        int x = v;
        #pragma unroll
        for (int off = 1; off < 32; off <<= 1) {
            int y = __shfl_up_sync(0xffffffffu, x, off);
            if (lane >= off) x += y;
        }
        if (i < nb) g_bsum[i] = x - v + run;     // exclusive + carry
        run += __shfl_sync(0xffffffffu, x, 31);
    }
    if (lane == 0) g_rowptr[n] = run;
}

// Phase C: add block offsets
__global__ void k_scanC(int n) {
    int i = blockIdx.x * SCAN_B + threadIdx.x;
    if (i < n) g_rowptr[i] += g_bsum[blockIdx.x];
}

__global__ void k_scatter(const void* __restrict__ ei, int E) {
    int e = blockIdx.x * blockDim.x + threadIdx.x;
    if (e < E) {
        int d = load_idx(ei, (long long)e + E);
        int s = load_idx(ei, e);
        int pos = g_rowptr[d] + atomicAdd(&g_fill[d], 1);
        g_csr[pos] = s;
    }
}

// ---------------- GEMM1: hs1 = bf16((x @ W1) * dinv[row]) ------------------
// block: 128 rows x 128 cols, 256 threads, 8x8 microtile, full K=128 in smem
__global__ void k_gemm1(const float* __restrict__ x,
                        const float* __restrict__ W, int n) {
    extern __shared__ float sm[];
    float* ws = sm;           // [k][c] 128x128
    float* xs = sm + 16384;   // [k][r] 128x128 (transposed x tile)
    int tid = threadIdx.x;
    int row0 = blockIdx.x * 128;

    for (int i = tid; i < 4096; i += 256)
        ((float4*)ws)[i] = ((const float4*)W)[i];

    for (int i = tid; i < 4096; i += 256) {
        int k4 = i >> 7, r = i & 127;
        float4 v = make_float4(0.f, 0.f, 0.f, 0.f);
        int row = row0 + r;
        if (row < n) v = ((const float4*)x)[(size_t)row * 32 + k4];
        xs[(k4 * 4 + 0) * 128 + r] = v.x;
        xs[(k4 * 4 + 1) * 128 + r] = v.y;
        xs[(k4 * 4 + 2) * 128 + r] = v.z;
        xs[(k4 * 4 + 3) * 128 + r] = v.w;
    }
    __syncthreads();

    int tx = tid & 15, ty = tid >> 4;
    float acc[8][8];
    #pragma unroll
    for (int i = 0; i < 8; i++)
        #pragma unroll
        for (int j = 0; j < 8; j++) acc[i][j] = 0.f;

    #pragma unroll 4
    for (int k = 0; k < 128; k++) {
        float4 a0 = *(const float4*)&xs[k * 128 + ty * 8];
        float4 a1 = *(const float4*)&xs[k * 128 + ty * 8 + 4];
        float4 b0 = *(const float4*)&ws[k * 128 + tx * 8];
        float4 b1 = *(const float4*)&ws[k * 128 + tx * 8 + 4];
        float a[8] = {a0.x, a0.y, a0.z, a0.w, a1.x, a1.y, a1.z, a1.w};
        float b[8] = {b0.x, b0.y, b0.z, b0.w, b1.x, b1.y, b1.z, b1.w};
        #pragma unroll
        for (int i = 0; i < 8; i++)
            #pragma unroll
            for (int j = 0; j < 8; j++)
                acc[i][j] = fmaf(a[i], b[j], acc[i][j]);
    }

    #pragma unroll
    for (int i = 0; i < 8; i++) {
        int row = row0 + ty * 8 + i;
        if (row < n) {
            float di = g_dinv[row];
            __nv_bfloat162 p0 = __floats2bfloat162_rn(acc[i][0] * di, acc[i][1] * di);
            __nv_bfloat162 p1 = __floats2bfloat162_rn(acc[i][2] * di, acc[i][3] * di);
            __nv_bfloat162 p2 = __floats2bfloat162_rn(acc[i][4] * di, acc[i][5] * di);
            __nv_bfloat162 p3 = __floats2bfloat162_rn(acc[i][6] * di, acc[i][7] * di);
            uint4 pk;
            pk.x = *(unsigned int*)&p0;
            pk.y = *(unsigned int*)&p1;
            pk.z = *(unsigned int*)&p2;
            pk.w = *(unsigned int*)&p3;
            ((uint4*)g_bufA)[(size_t)row * 16 + tx] = pk;
        }
    }
}

// ---------------- Agg1: h1r = relu(dinv[d]*(hs1[d] + sum_in hs1[s]) + b1) --
__device__ __forceinline__ void bf4_acc(float* a, uint2 v) {
    __nv_bfloat162 lo = *(__nv_bfloat162*)&v.x;
    __nv_bfloat162 hi = *(__nv_bfloat162*)&v.y;
    float2 f0 = __bfloat1622float2(lo);
    float2 f1 = __bfloat1622float2(hi);
    a[0] += f0.x; a[1] += f0.y; a[2] += f1.x; a[3] += f1.y;
}

__global__ void k_agg1(const float* __restrict__ b1, int n) {
    int w = (blockIdx.x * blockDim.x + threadIdx.x) >> 5;
    int lane = threadIdx.x & 31;
    if (w >= n) return;
    int d = w;
    const uint2* A = (const uint2*)g_bufA;   // row stride = 32 uint2
    float a0[4] = {0, 0, 0, 0}, a1[4] = {0, 0, 0, 0};
    float a2[4] = {0, 0, 0, 0}, a3[4] = {0, 0, 0, 0};
    bf4_acc(a0, A[(size_t)d * 32 + lane]);   // self loop
    int beg = g_rowptr[d], end = g_rowptr[d + 1];
    int e = beg;
    for (; e + 4 <= end; e += 4) {
        int s0 = g_csr[e], s1 = g_csr[e + 1], s2 = g_csr[e + 2], s3 = g_csr[e + 3];
        uint2 v0 = A[(size_t)s0 * 32 + lane];
        uint2 v1 = A[(size_t)s1 * 32 + lane];
        uint2 v2 = A[(size_t)s2 * 32 + lane];
        uint2 v3 = A[(size_t)s3 * 32 + lane];
        bf4_acc(a0, v0); bf4_acc(a1, v1); bf4_acc(a2, v2); bf4_acc(a3, v3);
    }
    for (; e < end; e++)
        bf4_acc(a0, A[(size_t)g_csr[e] * 32 + lane]);
    float di = g_dinv[d];
    float4 bb = ((const float4*)b1)[lane];
    float4 r;
    r.x = fmaxf(fmaf((a0[0] + a1[0]) + (a2[0] + a3[0]), di, bb.x), 0.f);
    r.y = fmaxf(fmaf((a0[1] + a1[1]) + (a2[1] + a3[1]), di, bb.y), 0.f);
    r.z = fmaxf(fmaf((a0[2] + a1[2]) + (a2[2] + a3[2]), di, bb.z), 0.f);
    r.w = fmaxf(fmaf((a0[3] + a1[3]) + (a2[3] + a3[3]), di, bb.w), 0.f);
    ((float4*)g_bufB)[(size_t)d * 32 + lane] = r;
}

// ---------------- GEMM2: hs2 = (h1r @ W2) * dinv, warp per row -------------
__global__ void k_gemm2(const float* __restrict__ W2, int n) {
    __shared__ float w2t[10 * 128];   // [c][k]
    int tid = threadIdx.x;
    for (int i = tid; i < 1280; i += 256) {
        int k = i / 10, c = i % 10;   // W2 row-major [k][c]
        w2t[c * 128 + k] = W2[i];
    }
    __syncthreads();
    int w = (blockIdx.x * blockDim.x + tid) >> 5;
    int lane = tid & 31;
    if (w >= n) return;
    int r = w;
    float4 h = ((const float4*)g_bufB)[(size_t)r * 32 + lane];
    float p[10];
    #pragma unroll
    for (int c = 0; c < 10; c++) {
        float s = h.x * w2t[c * 128 + lane * 4]
                + h.y * w2t[c * 128 + lane * 4 + 1]
                + h.z * w2t[c * 128 + lane * 4 + 2]
                + h.w * w2t[c * 128 + lane * 4 + 3];
        #pragma unroll
        for (int off = 16; off; off >>= 1)
            s += __shfl_xor_sync(0xffffffffu, s, off);
        p[c] = s;
    }
    float di = g_dinv[r];
    float val = 0.f;
    #pragma unroll
    for (int c = 0; c < 10; c++)
        if (lane == c) val = p[c];
    if (lane < 16)
        g_bufC[(size_t)r * 16 + lane] = (lane < 10) ? val * di : 0.f;
}

// ---------------- Agg2 + bias + softmax, half-warp per node ----------------
__global__ void k_agg2(const float* __restrict__ b2, float* __restrict__ out, int n) {
    int tid = threadIdx.x;
    int hw = (blockIdx.x * blockDim.x + tid) >> 4;
    int c = tid & 15;
    if (hw >= n) return;
    int d = hw;
    const float* C = g_bufC;
    float acc0 = C[(size_t)d * 16 + c];   // self loop
    float acc1 = 0.f, acc2 = 0.f, acc3 = 0.f;
    int beg = g_rowptr[d], end = g_rowptr[d + 1];
    int e = beg;
    for (; e + 4 <= end; e += 4) {
        int s0 = g_csr[e], s1 = g_csr[e + 1], s2 = g_csr[e + 2], s3 = g_csr[e + 3];
        acc0 += C[(size_t)s0 * 16 + c];
        acc1 += C[(size_t)s1 * 16 + c];
        acc2 += C[(size_t)s2 * 16 + c];
        acc3 += C[(size_t)s3 * 16 + c];
    }
    for (; e < end; e++)
        acc0 += C[(size_t)g_csr[e] * 16 + c];
    float acc = (acc0 + acc1) + (acc2 + acc3);
    float bc = (c < 10) ? b2[c] : 0.f;
    float logit = (c < 10) ? fmaf(acc, g_dinv[d], bc) : -1e30f;
    float m = logit;
    #pragma unroll
    for (int off = 8; off; off >>= 1)
        m = fmaxf(m, __shfl_xor_sync(0xffffffffu, m, off));
    float ex = (c < 10) ? __expf(logit - m) : 0.f;
    float ssum = ex;
    #pragma unroll
    for (int off = 8; off; off >>= 1)
        ssum += __shfl_xor_sync(0xffffffffu, ssum, off);
    if (c < 10) out[(size_t)d * 10 + c] = ex / ssum;
}

// ---------------- launch ---------------------------------------------------
extern "C" void kernel_launch(void* const* d_in, const int* in_sizes, int n_in,
                              void* d_out, int out_size) {
    const float* x  = (const float*)d_in[0];
    const void*  ei = d_in[1];
    const float* W1 = (const float*)d_in[2];
    const float* b1 = (const float*)d_in[3];
    const float* W2 = (const float*)d_in[4];
    const float* b2 = (const float*)d_in[5];
    int N = in_sizes[0] / 128;
    int E = in_sizes[1] / 2;
    int NB = (N + SCAN_B - 1) / SCAN_B;

    cudaFuncSetAttribute(k_gemm1, cudaFuncAttributeMaxDynamicSharedMemorySize, 131072);

    k_detect <<<1, 256>>>(ei, E, N);
    k_zero   <<<(N + 255) / 256, 256>>>(N);
    k_count  <<<(E + 255) / 256, 256>>>(ei, E);
    k_scanA  <<<NB, SCAN_B>>>(N);
    k_scanB  <<<1, 32>>>(NB, N);
    k_scanC  <<<NB, SCAN_B>>>(N);
    k_scatter<<<(E + 255) / 256, 256>>>(ei, E);
    k_gemm1  <<<(N + 127) / 128, 256, 131072>>>(x, W1, N);
    k_agg1   <<<(N + 7) / 8, 256>>>(b1, N);
    k_gemm2  <<<(N + 7) / 8, 256>>>(W2, N);
    k_agg2   <<<(N + 15) / 16, 256>>>(b2, (float*)d_out, N);
}